// round 8
// baseline (speedup 1.0000x reference)
#include <cuda_runtime.h>
#include <cuda_bf16.h>
#include <cstdint>
#include <cfloat>

// GaussianLayer: out[m,k] = tanh(scale[k]) * exp(-zz - mm + 2*zm)
//   d[k,i]  = 0.1 + 0.9*sigmoid(diag[k,i]),  d in (0.1, 1.0)
//   exponent = -sum_i d[k,i]*(z[m,i]-mean[k,i])^2  <= 0 (exact identity)
// Weighted Cauchy-Schwarz (d <= 1):
//   sum_i d*(z-mean)^2 >= (sqrt(mm[k]) - ||z_m||)^2  when sqrt(mm[k]) >= ||z_m||
// If sqrt(mm[k]) > ||z_m|| + 12, exponent < -144 < -104 => expf underflows
// to exactly +-0.0f. Elements failing the bound use the exact fp32
// reference expression.
//
// Two graph nodes. Prep uses grid-stride loops (4 rows per warp) to
// amortize the cross-CTA L1tex-queue spread that capped the churny
// one-row-per-warp version at ~4.5 TB/s.

#define MAX_M 16384
#define MAX_OUT 2048

__device__ float g_zn[MAX_M];    // ||z_m||
__device__ float g_sq[MAX_OUT];  // sqrt(sum_i d*mean^2)
__device__ float g_ts[MAX_OUT];  // tanh(scale)

// ================= Kernel 1: prep (grid-stride) ===========================
// Blocks [0,nbz): z row norms; blocks [nbz,nbz+nbk): k-stats.
// Each warp loops over rows/features with stride = total warps in its part.
__global__ void __launch_bounds__(256) prep_kernel(
    const float* __restrict__ z,
    const float* __restrict__ diag, const float* __restrict__ mean,
    const float* __restrict__ scale,
    int m, int out_f, int in_f, int nbz, int zwarps, int kwarps)
{
    int wid = threadIdx.x >> 5;
    int lane = threadIdx.x & 31;
    int n4 = in_f >> 2;

    if ((int)blockIdx.x < nbz) {
        int gw = blockIdx.x * 8 + wid;
        for (int row = gw; row < m; row += zwarps) {
            const float4* rp = reinterpret_cast<const float4*>(z + (size_t)row * in_f);
            float s = 0.0f;
            if (n4 == 256) {
                float4 v[8];
                #pragma unroll
                for (int j = 0; j < 8; j++) v[j] = __ldcs(&rp[lane + 32 * j]);
                #pragma unroll
                for (int j = 0; j < 8; j++)
                    s += v[j].x * v[j].x + v[j].y * v[j].y
                       + v[j].z * v[j].z + v[j].w * v[j].w;
            } else {
                for (int i = lane; i < n4; i += 32) {
                    float4 v = __ldcs(&rp[i]);
                    s += v.x * v.x + v.y * v.y + v.z * v.z + v.w * v.w;
                }
            }
            #pragma unroll
            for (int o = 16; o; o >>= 1) s += __shfl_xor_sync(0xFFFFFFFFu, s, o);
            if (lane == 0) g_zn[row] = sqrtf(s);
        }
    } else {
        // Fast sigmoid feeds only the conservative bound (margin >> error);
        // the exact fallback never uses these values.
        int gw = (blockIdx.x - nbz) * 8 + wid;
        for (int k = gw; k < out_f; k += kwarps) {
            const float4* dr = reinterpret_cast<const float4*>(diag + (size_t)k * in_f);
            const float4* mr = reinterpret_cast<const float4*>(mean + (size_t)k * in_f);
            float s = 0.0f;
            #pragma unroll 4
            for (int i = lane; i < n4; i += 32) {
                float4 dv = __ldcs(&dr[i]);
                float4 mv = __ldcs(&mr[i]);
                float d0 = 0.1f + __fdividef(0.9f, 1.0f + __expf(-dv.x));
                float d1 = 0.1f + __fdividef(0.9f, 1.0f + __expf(-dv.y));
                float d2 = 0.1f + __fdividef(0.9f, 1.0f + __expf(-dv.z));
                float d3 = 0.1f + __fdividef(0.9f, 1.0f + __expf(-dv.w));
                s += d0 * mv.x * mv.x + d1 * mv.y * mv.y
                   + d2 * mv.z * mv.z + d3 * mv.w * mv.w;
            }
            #pragma unroll
            for (int o = 16; o; o >>= 1) s += __shfl_xor_sync(0xFFFFFFFFu, s, o);
            if (lane == 0) {
                g_sq[k] = sqrtf(s);
                g_ts[k] = tanhf(scale[k]);
            }
        }
    }
}

// ================= Fallback: exact fp32 reference expression ==============
__device__ __noinline__ float slow_elem(
    const float* __restrict__ z, const float* __restrict__ diag,
    const float* __restrict__ mean, int mrow, int k, int in_f)
{
    const float* zr = z + (size_t)mrow * in_f;
    const float* dr = diag + (size_t)k * in_f;
    const float* mr = mean + (size_t)k * in_f;
    float zz = 0.0f, zm = 0.0f, mm = 0.0f;
    for (int i = 0; i < in_f; i++) {
        float d = 0.1f + 0.9f / (1.0f + expf(-dr[i]));
        float zi = zr[i];
        float mi = mr[i];
        zz += d * zi * zi;
        zm += zi * d * mi;
        mm += d * mi * mi;
    }
    return g_ts[k] * expf(-zz - mm + 2.0f * zm);
}

// ================= Kernel 2a: row-tiled streaming output ==================
// Block of 256 threads covers R rows (R*n4row == 2048 float4). Thread owns
// one row segment: ONE g_zn load + 8 independent {q-load, cmp, STG.128.cs}.
__global__ void __launch_bounds__(256) out_tiled_kernel(
    const float* __restrict__ z, const float* __restrict__ diag,
    const float* __restrict__ mean, float* __restrict__ out,
    int m, int out_f, int in_f, int n4row, int rows_per_block, int tpr)
{
    const float4* sq4 = reinterpret_cast<const float4*>(g_sq);
    float4* out4 = reinterpret_cast<float4*>(out);
    const float4 zero4 = make_float4(0.0f, 0.0f, 0.0f, 0.0f);

    int tid = threadIdx.x;
    int rlocal = tid / tpr;
    int col0 = tid - rlocal * tpr;
    int row = blockIdx.x * rows_per_block + rlocal;
    if (row >= m) return;

    float thr = g_zn[row] + 12.0f;
    size_t rbase = (size_t)row * n4row;

    #pragma unroll
    for (int j = 0; j < 8; j++) {
        int k4 = col0 + j * tpr;
        float4 q = sq4[k4];                       // L1-resident 8 KB table
        float qmin = fminf(fminf(q.x, q.y), fminf(q.z, q.w));
        if (qmin > thr) {
            __stcs(&out4[rbase + k4], zero4);
        } else {
            int kbase = k4 * 4;
            float4 r4;
            r4.x = (q.x > thr) ? 0.0f : slow_elem(z, diag, mean, row, kbase + 0, in_f);
            r4.y = (q.y > thr) ? 0.0f : slow_elem(z, diag, mean, row, kbase + 1, in_f);
            r4.z = (q.z > thr) ? 0.0f : slow_elem(z, diag, mean, row, kbase + 2, in_f);
            r4.w = (q.w > thr) ? 0.0f : slow_elem(z, diag, mean, row, kbase + 3, in_f);
            out4[rbase + k4] = r4;
        }
    }
}

// ================= Kernel 2b: flat output (generic fallback) ==============
#define OU 8
__global__ void __launch_bounds__(256) out_flat_kernel(
    const float* __restrict__ z, const float* __restrict__ diag,
    const float* __restrict__ mean, float* __restrict__ out,
    int m, int out_f, int in_f, int n4row, int n4tot)
{
    const float4* sq4 = reinterpret_cast<const float4*>(g_sq);
    float4* out4 = reinterpret_cast<float4*>(out);
    const float4 zero4 = make_float4(0.0f, 0.0f, 0.0f, 0.0f);
    int base = blockIdx.x * (256 * OU) + threadIdx.x;

    #pragma unroll
    for (int j = 0; j < OU; j++) {
        int idx = base + j * 256;
        if (idx >= n4tot) continue;
        int row = (int)((unsigned)idx / (unsigned)n4row);
        int k4 = idx - row * n4row;
        float thr = g_zn[row] + 12.0f;
        float4 q = sq4[k4];
        float qmin = fminf(fminf(q.x, q.y), fminf(q.z, q.w));
        if (qmin > thr) {
            __stcs(&out4[idx], zero4);
        } else {
            int kbase = k4 * 4;
            float4 r4;
            r4.x = (q.x > thr) ? 0.0f : slow_elem(z, diag, mean, row, kbase + 0, in_f);
            r4.y = (q.y > thr) ? 0.0f : slow_elem(z, diag, mean, row, kbase + 1, in_f);
            r4.z = (q.z > thr) ? 0.0f : slow_elem(z, diag, mean, row, kbase + 2, in_f);
            r4.w = (q.w > thr) ? 0.0f : slow_elem(z, diag, mean, row, kbase + 3, in_f);
            out4[idx] = r4;
        }
    }
}

extern "C" void kernel_launch(void* const* d_in, const int* in_sizes, int n_in,
                              void* d_out, int out_size)
{
    const float* z     = (const float*)d_in[0];  // (m, in_f)
    const float* diag  = (const float*)d_in[1];  // (out_f, in_f)
    const float* mean  = (const float*)d_in[2];  // (out_f, in_f, 1)
    const float* scale = (const float*)d_in[3];  // (out_f,)
    float* out = (float*)d_out;

    int out_f = in_sizes[3];
    int in_f  = in_sizes[1] / out_f;
    int m     = in_sizes[0] / in_f;

    // Kernel 1: grid-stride prep. ~4 CTAs/SM; each warp loops ~4 rows.
    int nbz = 512, nbk = 64;
    int zwarps = nbz * 8, kwarps = nbk * 8;
    prep_kernel<<<nbz + nbk, 256>>>(z, diag, mean, scale, m, out_f, in_f,
                                    nbz, zwarps, kwarps);

    // Kernel 2: output. Row-tiled when shapes permit, else flat.
    int n4row = out_f >> 2;
    int n4tot = (int)(((size_t)m * out_f) >> 2);
    bool tiled_ok = (n4row > 0) && (2048 % n4row == 0);
    int rows_per_block = tiled_ok ? 2048 / n4row : 0;
    int tpr = tiled_ok && rows_per_block <= 256 ? 256 / rows_per_block : 0;
    // need: tpr divides n4row into exactly 8 chunks
    if (tiled_ok && tpr > 0 && tpr * 8 == n4row) {
        int nb = (m + rows_per_block - 1) / rows_per_block;
        out_tiled_kernel<<<nb, 256>>>(z, diag, mean, out, m, out_f, in_f,
                                      n4row, rows_per_block, tpr);
    } else {
        int per_block = 256 * OU;
        int nb = (n4tot + per_block - 1) / per_block;
        out_flat_kernel<<<nb, 256>>>(z, diag, mean, out, m, out_f, in_f,
                                     n4row, n4tot);
    }
}

// round 9
// speedup vs baseline: 1.2353x; 1.2353x over previous
#include <cuda_runtime.h>
#include <cuda_bf16.h>
#include <cstdint>
#include <cfloat>

// GaussianLayer: out[m,k] = tanh(scale[k]) * exp(-zz - mm + 2*zm)
//   d[k,i]  = 0.1 + 0.9*sigmoid(diag[k,i]),  d in (0.1, 1.0)
//   exponent = -sum_i d[k,i]*(z[m,i]-mean[k,i])^2  <= 0 (exact identity)
// Weighted Cauchy-Schwarz (d <= 1):
//   sum_i d*(z-mean)^2 >= (sqrt(mm[k]) - ||z_m||)^2  when sqrt(mm[k]) >= ||z_m||
// If sqrt(mm[k]) > ||z_m|| + 12, exponent < -144 < -104 => expf underflows
// to exactly +-0.0f. Elements failing the bound use the exact fp32
// reference expression.
//
// Structure (2 nodes):
//   K1 kstats: sqrt(sum d*mean^2), tanh(scale)            [16 MB read]
//   K2 fused:  one WARP per m-row, no block barriers:
//              read own z-row (8 loads in flight) -> shfl-reduce norm ->
//              stream the row's bound-tested stores. z-read and out-write
//              interleave on HBM in a single wave instead of two serialized
//              half-utilized waves (read wave caps ~4.5 TB/s alone).

#define MAX_OUT 2048

__device__ float g_sq[MAX_OUT];  // sqrt(sum_i d*mean^2)
__device__ float g_ts[MAX_OUT];  // tanh(scale)

// ================= Kernel 1: k-stats ======================================
// One warp per out-feature. Fast sigmoid feeds only the conservative bound
// (margin >> approx error); the exact fallback never uses these values.
__global__ void __launch_bounds__(256) kstats_kernel(
    const float* __restrict__ diag, const float* __restrict__ mean,
    const float* __restrict__ scale, int out_f, int in_f)
{
    int k = blockIdx.x * 8 + (threadIdx.x >> 5);
    int lane = threadIdx.x & 31;
    if (k >= out_f) return;
    int n4 = in_f >> 2;
    const float4* dr = reinterpret_cast<const float4*>(diag + (size_t)k * in_f);
    const float4* mr = reinterpret_cast<const float4*>(mean + (size_t)k * in_f);
    float s = 0.0f;
    #pragma unroll 4
    for (int i = lane; i < n4; i += 32) {
        float4 dv = __ldcs(&dr[i]);
        float4 mv = __ldcs(&mr[i]);
        float d0 = 0.1f + __fdividef(0.9f, 1.0f + __expf(-dv.x));
        float d1 = 0.1f + __fdividef(0.9f, 1.0f + __expf(-dv.y));
        float d2 = 0.1f + __fdividef(0.9f, 1.0f + __expf(-dv.z));
        float d3 = 0.1f + __fdividef(0.9f, 1.0f + __expf(-dv.w));
        s += d0 * mv.x * mv.x + d1 * mv.y * mv.y
           + d2 * mv.z * mv.z + d3 * mv.w * mv.w;
    }
    #pragma unroll
    for (int o = 16; o; o >>= 1) s += __shfl_xor_sync(0xFFFFFFFFu, s, o);
    if (lane == 0) {
        g_sq[k] = sqrtf(s);
        g_ts[k] = tanhf(scale[k]);
    }
}

// ================= Fallback: exact fp32 reference expression ==============
__device__ __noinline__ float slow_elem(
    const float* __restrict__ z, const float* __restrict__ diag,
    const float* __restrict__ mean, int mrow, int k, int in_f)
{
    const float* zr = z + (size_t)mrow * in_f;
    const float* dr = diag + (size_t)k * in_f;
    const float* mr = mean + (size_t)k * in_f;
    float zz = 0.0f, zm = 0.0f, mm = 0.0f;
    for (int i = 0; i < in_f; i++) {
        float d = 0.1f + 0.9f / (1.0f + expf(-dr[i]));
        float zi = zr[i];
        float mi = mr[i];
        zz += d * zi * zi;
        zm += zi * d * mi;
        mm += d * mi * mi;
    }
    return g_ts[k] * expf(-zz - mm + 2.0f * zm);
}

// ================= Kernel 2: fused per-warp norm + output =================
// 256 threads = 8 independent warps, each owning one m-row. NO __syncthreads.
__global__ void __launch_bounds__(256) fused_kernel(
    const float* __restrict__ z, const float* __restrict__ diag,
    const float* __restrict__ mean, float* __restrict__ out,
    int m, int out_f, int in_f, int n4row)
{
    int lane = threadIdx.x & 31;
    int row = blockIdx.x * 8 + (threadIdx.x >> 5);
    if (row >= m) return;

    // ---- Phase 1 (warp-local): ||z_row|| with 8 loads in flight ----
    int n4in = in_f >> 2;
    const float4* rp = reinterpret_cast<const float4*>(z + (size_t)row * in_f);
    float s = 0.0f;
    if (n4in == 256) {
        float4 v[8];
        #pragma unroll
        for (int j = 0; j < 8; j++) v[j] = __ldcs(&rp[lane + 32 * j]);
        #pragma unroll
        for (int j = 0; j < 8; j++)
            s += v[j].x * v[j].x + v[j].y * v[j].y
               + v[j].z * v[j].z + v[j].w * v[j].w;
    } else {
        for (int i = lane; i < n4in; i += 32) {
            float4 v = __ldcs(&rp[i]);
            s += v.x * v.x + v.y * v.y + v.z * v.z + v.w * v.w;
        }
    }
    #pragma unroll
    for (int o = 16; o; o >>= 1) s += __shfl_xor_sync(0xFFFFFFFFu, s, o);
    float thr = sqrtf(s) + 12.0f;

    // ---- Phase 2 (warp-local): bound-tested streaming stores ----
    const float4* sq4 = reinterpret_cast<const float4*>(g_sq);
    float4* orow = reinterpret_cast<float4*>(out) + (size_t)row * n4row;
    const float4 zero4 = make_float4(0.0f, 0.0f, 0.0f, 0.0f);

    #pragma unroll 4
    for (int k4 = lane; k4 < n4row; k4 += 32) {
        float4 q = sq4[k4];                       // L1-resident 8 KB table
        float qmin = fminf(fminf(q.x, q.y), fminf(q.z, q.w));
        if (qmin > thr) {
            __stcs(&orow[k4], zero4);
        } else {
            int kbase = k4 * 4;
            float4 r4;
            r4.x = (q.x > thr) ? 0.0f : slow_elem(z, diag, mean, row, kbase + 0, in_f);
            r4.y = (q.y > thr) ? 0.0f : slow_elem(z, diag, mean, row, kbase + 1, in_f);
            r4.z = (q.z > thr) ? 0.0f : slow_elem(z, diag, mean, row, kbase + 2, in_f);
            r4.w = (q.w > thr) ? 0.0f : slow_elem(z, diag, mean, row, kbase + 3, in_f);
            orow[k4] = r4;
        }
    }
    // Scalar tail for out_f not divisible by 4 (not hit for out_f=2048).
    int ktail = n4row * 4;
    for (int k = ktail + lane; k < out_f; k += 32) {
        float v = (g_sq[k] > thr) ? 0.0f
                                  : slow_elem(z, diag, mean, row, k, in_f);
        out[(size_t)row * out_f + k] = v;
    }
}

extern "C" void kernel_launch(void* const* d_in, const int* in_sizes, int n_in,
                              void* d_out, int out_size)
{
    const float* z     = (const float*)d_in[0];  // (m, in_f)
    const float* diag  = (const float*)d_in[1];  // (out_f, in_f)
    const float* mean  = (const float*)d_in[2];  // (out_f, in_f, 1)
    const float* scale = (const float*)d_in[3];  // (out_f,)
    float* out = (float*)d_out;

    int out_f = in_sizes[3];
    int in_f  = in_sizes[1] / out_f;
    int m     = in_sizes[0] / in_f;

    // Kernel 1: k-stats (one warp per out-feature)
    int nb_k = (out_f + 7) / 8;
    kstats_kernel<<<nb_k, 256>>>(diag, mean, scale, out_f, in_f);

    // Kernel 2: fused per-warp z-norm + output (one warp per row)
    int n4row = out_f >> 2;
    int nb = (m + 7) / 8;
    fused_kernel<<<nb, 256>>>(z, diag, mean, out, m, out_f, in_f, n4row);
}